// round 17
// baseline (speedup 1.0000x reference)
#include <cuda_runtime.h>
#include <cuda_bf16.h>
#include <cuda_fp16.h>
#include <math.h>
#include <cstdint>

#define B_    2
#define N_    1024
#define DIM_  512
#define NH_   8
#define HD_   64
#define WIN_  64
#define M_    (B_ * N_)      // 2048
#define DFF_  (4 * DIM_)     // 2048
#define EPSV  1e-7f

// ------------------------ scratch (device globals; no allocation) ------------
__device__ __half g_xnh [M_ * DIM_];    // LN1 out (half)
__device__ __half g_q   [M_ * DIM_];    // QKV outs (half)
__device__ __half g_k   [M_ * DIM_];
__device__ __half g_v   [M_ * DIM_];
__device__ __half g_qh  [B_ * NH_ * N_ * HD_];   // prep outs (half)
__device__ __half g_kh  [B_ * NH_ * N_ * HD_];
__device__ __half g_vt  [B_ * NH_ * N_ * HD_];
__device__ __half g_attnh[M_ * DIM_];   // attention out (half)
__device__ float  g_xout[M_ * DIM_];
__device__ __half g_hhh [M_ * DIM_];    // LN2 out (half)
__device__ __half g_midh[M_ * DFF_];    // FFN mid (half)
// half weights, concatenated
#define WH_Q 0
#define WH_K 262144
#define WH_V 524288
#define WH_O 786432
#define WH_1 1048576
#define WH_2 2097152
__device__ __half g_wh[3145728];

// ------------------------ helpers -------------------------------------------
__device__ __forceinline__ float warpsum(float v) {
#pragma unroll
    for (int o = 16; o > 0; o >>= 1) v += __shfl_xor_sync(0xffffffffu, v, o);
    return v;
}
__device__ __forceinline__ float warpmax(float v) {
#pragma unroll
    for (int o = 16; o > 0; o >>= 1) v = fmaxf(v, __shfl_xor_sync(0xffffffffu, v, o));
    return v;
}
__device__ __forceinline__ float sqrt_fast(float x) {
    float r;
    asm("sqrt.approx.f32 %0, %1;" : "=f"(r) : "f"(x));
    return r;
}
__device__ __forceinline__ uint32_t packh2(float lo, float hi) {
    __half2 h = __floats2half2_rn(lo, hi);
    return *(uint32_t*)&h;
}
__device__ __forceinline__ float2 unpackh2(uint32_t u) {
    return __half22float2(*(__half2*)&u);
}
__device__ __forceinline__ __half2 ash2(uint32_t u) { return *(__half2*)&u; }
// fast tanh for x >= 0:  tanh(x) = 1 - 2/(1+e^{2x})
__device__ __forceinline__ float tanh_pos(float x) {
    return 1.f - __fdividef(2.f, 1.f + __expf(2.f * x));
}
// fp16 tensor-core mma: D(f32) += A(f16,16x16) * B(f16,16x8)
__device__ __forceinline__ void mma_f16(float4& c, uint32_t a0, uint32_t a1,
                                        uint32_t a2, uint32_t a3,
                                        uint32_t b0, uint32_t b1) {
    asm volatile(
        "mma.sync.aligned.m16n8k16.row.col.f32.f16.f16.f32 "
        "{%0,%1,%2,%3},{%4,%5,%6,%7},{%8,%9},{%0,%1,%2,%3};\n"
        : "+f"(c.x), "+f"(c.y), "+f"(c.z), "+f"(c.w)
        : "r"(a0), "r"(a1), "r"(a2), "r"(a3), "r"(b0), "r"(b1));
}

// ------------------------ fused LN1 + weight convert -------------------------
__global__ __launch_bounds__(128) void ln1_cvtw_kernel(
    const float* __restrict__ x, const float* __restrict__ s,
    const float* __restrict__ bsh, __half* __restrict__ out,
    const float* __restrict__ Wq, const float* __restrict__ Wk,
    const float* __restrict__ Wv, const float* __restrict__ Wo,
    const float* __restrict__ W1, const float* __restrict__ W2,
    __half* __restrict__ wh) {
    if (blockIdx.x < 2048) {
        int row = blockIdx.x;
        const float* xr = x + (size_t)row * DIM_;
        float v[4];
        float sum = 0.f, sq = 0.f;
#pragma unroll
        for (int i = 0; i < 4; i++) {
            v[i] = xr[threadIdx.x + i * 128];
            sum += v[i];
            sq  += v[i] * v[i];
        }
        __shared__ float red0[4], red1[4];
        sum = warpsum(sum); sq = warpsum(sq);
        int warp = threadIdx.x >> 5, lane = threadIdx.x & 31;
        if (lane == 0) { red0[warp] = sum; red1[warp] = sq; }
        __syncthreads();
        sum = red0[0] + red0[1] + red0[2] + red0[3];
        sq  = red1[0] + red1[1] + red1[2] + red1[3];
        float mean = sum * (1.0f / DIM_);
        float var  = sq * (1.0f / DIM_) - mean * mean;
        float inv  = rsqrtf(var + 1e-6f);
        __half* orow = out + (size_t)row * DIM_;
#pragma unroll
        for (int i = 0; i < 4; i++) {
            int d = threadIdx.x + i * 128;
            orow[d] = __float2half_rn((v[i] - mean) * inv * s[d] + bsh[d]);
        }
    } else {
        long i = ((long)(blockIdx.x - 2048) * 128 + threadIdx.x) * 4;
        if (i >= 3145728) return;
        const float* src;
        long off;
        if      (i <  262144) { src = Wq; off = i; }
        else if (i <  524288) { src = Wk; off = i - 262144; }
        else if (i <  786432) { src = Wv; off = i - 524288; }
        else if (i < 1048576) { src = Wo; off = i - 786432; }
        else if (i < 2097152) { src = W1; off = i - 1048576; }
        else                  { src = W2; off = i - 2097152; }
        float4 v = *(const float4*)(src + off);
        *(uint2*)(wh + i) = make_uint2(packh2(v.x, v.y), packh2(v.z, v.w));
    }
}

// ------------------------ layernorm (half output) ----------------------------
__global__ void ln_kernel(const float* __restrict__ x, const float* __restrict__ s,
                          const float* __restrict__ bsh, __half* __restrict__ out) {
    int row = blockIdx.x;
    const float* xr = x + (size_t)row * DIM_;
    float v[4];
    float sum = 0.f, sq = 0.f;
#pragma unroll
    for (int i = 0; i < 4; i++) {
        v[i] = xr[threadIdx.x + i * 128];
        sum += v[i];
        sq  += v[i] * v[i];
    }
    __shared__ float red0[4], red1[4];
    sum = warpsum(sum); sq = warpsum(sq);
    int warp = threadIdx.x >> 5, lane = threadIdx.x & 31;
    if (lane == 0) { red0[warp] = sum; red1[warp] = sq; }
    __syncthreads();
    sum = red0[0] + red0[1] + red0[2] + red0[3];
    sq  = red1[0] + red1[1] + red1[2] + red1[3];
    float mean = sum * (1.0f / DIM_);
    float var  = sq * (1.0f / DIM_) - mean * mean;
    float inv  = rsqrtf(var + 1e-6f);
    __half* orow = out + (size_t)row * DIM_;
#pragma unroll
    for (int i = 0; i < 4; i++) {
        int d = threadIdx.x + i * 128;
        orow[d] = __float2half_rn((v[i] - mean) * inv * s[d] + bsh[d]);
    }
}

// ======================= 128x128 fp16 GEMM (QKV / FFN1) ======================
struct GSmem128 {
    uint2 Ap[2][2][4][132];  // [buf][ks16][tg][row 0..127]
    uint2 Bp[2][2][4][132];  // [buf][ks16][tg][col 0..127]
};

// EPI: 2 = gelu+bias (half out), 3 = +bias (half out)
template <int EPI>
__device__ __forceinline__ void gemm_core128(
    const __half* __restrict__ A, const __half* __restrict__ Bw,
    const float* __restrict__ bias, __half* __restrict__ Ch, int Nd, int Kd) {
    __shared__ GSmem128 sm;
    const int m0 = blockIdx.y * 128, n0 = blockIdx.x * 128;
    const int tid = threadIdx.x;
    const int lane = tid & 31, wid = tid >> 5;
    const int g = lane >> 2, tg = lane & 3;
    const int wm = wid >> 2, wn = wid & 3;       // warp grid 2x4

    const int arow = tid >> 1, akh = tid & 1;
    const __half* aPtr = A + (size_t)(m0 + arow) * Kd + akh * 16;
    const int btg = (tid >> 6) & 3, bcp = tid & 63;
    const __half* bPtr0 = Bw + (size_t)(2 * btg) * Nd + n0 + 2 * bcp;
    const __half* bPtr1 = bPtr0 + (size_t)16 * Nd;

    float4 acc[4][4];
#pragma unroll
    for (int i = 0; i < 4; i++)
#pragma unroll
        for (int j = 0; j < 4; j++) acc[i][j] = make_float4(0.f, 0.f, 0.f, 0.f);

    uint4 alo, ahi;
    uint32_t wv[2][4];
    alo = *(const uint4*)(aPtr);
    ahi = *(const uint4*)(aPtr + 8);
#pragma unroll
    for (int s = 0; s < 2; s++) {
        const __half* bp = s ? bPtr1 : bPtr0;
        wv[s][0] = *(const uint32_t*)(bp);
        wv[s][1] = *(const uint32_t*)(bp + Nd);
        wv[s][2] = *(const uint32_t*)(bp + 8 * Nd);
        wv[s][3] = *(const uint32_t*)(bp + 9 * Nd);
    }

    auto store_tile = [&](int buf) {
        sm.Ap[buf][akh][0][arow] = make_uint2(alo.x, ahi.x);
        sm.Ap[buf][akh][1][arow] = make_uint2(alo.y, ahi.y);
        sm.Ap[buf][akh][2][arow] = make_uint2(alo.z, ahi.z);
        sm.Ap[buf][akh][3][arow] = make_uint2(alo.w, ahi.w);
#pragma unroll
        for (int s = 0; s < 2; s++) {
            uint32_t lo0 = __byte_perm(wv[s][0], wv[s][1], 0x5410);
            uint32_t lo1 = __byte_perm(wv[s][0], wv[s][1], 0x7632);
            uint32_t hi0 = __byte_perm(wv[s][2], wv[s][3], 0x5410);
            uint32_t hi1 = __byte_perm(wv[s][2], wv[s][3], 0x7632);
            *(uint4*)&sm.Bp[buf][s][btg][2 * bcp] = make_uint4(lo0, hi0, lo1, hi1);
        }
    };

    store_tile(0);
    __syncthreads();

    const int nT = Kd >> 5;
    for (int t = 0; t < nT; t++) {
        const int buf = t & 1;
        const bool more = (t + 1 < nT);
        if (more) {
            const __half* ap = aPtr + (t + 1) * 32;
            alo = *(const uint4*)(ap);
            ahi = *(const uint4*)(ap + 8);
            const size_t koff = (size_t)(t + 1) * 32 * Nd;
#pragma unroll
            for (int s = 0; s < 2; s++) {
                const __half* bp = (s ? bPtr1 : bPtr0) + koff;
                wv[s][0] = *(const uint32_t*)(bp);
                wv[s][1] = *(const uint32_t*)(bp + Nd);
                wv[s][2] = *(const uint32_t*)(bp + 8 * Nd);
                wv[s][3] = *(const uint32_t*)(bp + 9 * Nd);
            }
        }
#pragma unroll
        for (int ks = 0; ks < 2; ks++) {
            uint2 fal[4], fah[4], fb[4];
#pragma unroll
            for (int mi = 0; mi < 4; mi++) {
                fal[mi] = sm.Ap[buf][ks][tg][wm * 64 + mi * 16 + g];
                fah[mi] = sm.Ap[buf][ks][tg][wm * 64 + mi * 16 + g + 8];
            }
#pragma unroll
            for (int nj = 0; nj < 4; nj++)
                fb[nj] = sm.Bp[buf][ks][tg][wn * 32 + nj * 8 + g];
#pragma unroll
            for (int mi = 0; mi < 4; mi++)
#pragma unroll
                for (int nj = 0; nj < 4; nj++)
                    mma_f16(acc[mi][nj],
                            fal[mi].x, fah[mi].x, fal[mi].y, fah[mi].y,
                            fb[nj].x, fb[nj].y);
        }
        if (more) store_tile(buf ^ 1);
        __syncthreads();
    }

#pragma unroll
    for (int mi = 0; mi < 4; mi++) {
        int r0 = m0 + wm * 64 + mi * 16 + g;
#pragma unroll
        for (int nj = 0; nj < 4; nj++) {
            int col = n0 + wn * 32 + nj * 8 + tg * 2;
            float2 bbv = *(const float2*)(bias + col);
            float4 a = acc[mi][nj];
            float2 o0 = make_float2(a.x + bbv.x, a.y + bbv.y);
            float2 o1 = make_float2(a.z + bbv.x, a.w + bbv.y);
            if (EPI == 2) {
                float t0 = o0.x, t1 = o0.y, t2 = o1.x, t3 = o1.y;
                o0.x = t0 / (1.f + __expf(-1.5957691216057308f * (t0 + 0.044715f * t0 * t0 * t0)));
                o0.y = t1 / (1.f + __expf(-1.5957691216057308f * (t1 + 0.044715f * t1 * t1 * t1)));
                o1.x = t2 / (1.f + __expf(-1.5957691216057308f * (t2 + 0.044715f * t2 * t2 * t2)));
                o1.y = t3 / (1.f + __expf(-1.5957691216057308f * (t3 + 0.044715f * t3 * t3 * t3)));
            }
            *(uint32_t*)(Ch + (size_t)r0 * Nd + col)       = packh2(o0.x, o0.y);
            *(uint32_t*)(Ch + (size_t)(r0 + 8) * Nd + col) = packh2(o1.x, o1.y);
        }
    }
}

__global__ __launch_bounds__(256, 2) void k_gemm_qkv(
    const __half* __restrict__ xn, const __half* __restrict__ wh,
    const float* __restrict__ bq, const float* __restrict__ bk,
    const float* __restrict__ bv,
    __half* __restrict__ q, __half* __restrict__ k, __half* __restrict__ v) {
    int z = blockIdx.z;
    const __half* W  = wh + ((z == 0) ? WH_Q : (z == 1) ? WH_K : WH_V);
    const float* bb  = (z == 0) ? bq : (z == 1) ? bk : bv;
    __half* o        = (z == 0) ? q  : (z == 1) ? k  : v;
    gemm_core128<3>(xn, W, bb, o, DIM_, DIM_);
}

__global__ __launch_bounds__(256, 2) void k_gemm128_gelu(
    const __half* __restrict__ A, const __half* __restrict__ W,
    const float* __restrict__ bias, __half* __restrict__ C, int Nd, int Kd) {
    gemm_core128<2>(A, W, bias, C, Nd, Kd);
}

// ======================= 128x64 fp16 GEMM (Wo / FFN2, +residual, f32 out) ====
struct GSmem64 {
    uint2 Ap[2][2][4][132];
    uint2 Bp[2][2][4][68];
};

__global__ __launch_bounds__(256, 3) void k_gemm64_res(
    const __half* __restrict__ A, const __half* __restrict__ Bw,
    const float* __restrict__ bias, const float* __restrict__ res,
    float* __restrict__ C, int Nd, int Kd) {
    __shared__ GSmem64 sm;
    const int m0 = blockIdx.y * 128, n0 = blockIdx.x * 64;
    const int tid = threadIdx.x;
    const int lane = tid & 31, wid = tid >> 5;
    const int g = lane >> 2, tg = lane & 3;
    const int wm = wid >> 1, wn = wid & 1;

    const int arow = tid >> 1, akh = tid & 1;
    const __half* aPtr = A + (size_t)(m0 + arow) * Kd + akh * 16;
    const int bks = tid >> 7, btg = (tid >> 5) & 3, bcp = tid & 31;
    const __half* bPtr = Bw + (size_t)(bks * 16 + 2 * btg) * Nd + n0 + 2 * bcp;

    float4 acc[2][4];
#pragma unroll
    for (int i = 0; i < 2; i++)
#pragma unroll
        for (int j = 0; j < 4; j++) acc[i][j] = make_float4(0.f, 0.f, 0.f, 0.f);

    uint4 alo, ahi;
    uint32_t w0, w1, w2, w3;
    alo = *(const uint4*)(aPtr);
    ahi = *(const uint4*)(aPtr + 8);
    w0 = *(const uint32_t*)(bPtr);
    w1 = *(const uint32_t*)(bPtr + Nd);
    w2 = *(const uint32_t*)(bPtr + 8 * Nd);
    w3 = *(const uint32_t*)(bPtr + 9 * Nd);

    auto store_tile = [&](int buf) {
        sm.Ap[buf][akh][0][arow] = make_uint2(alo.x, ahi.x);
        sm.Ap[buf][akh][1][arow] = make_uint2(alo.y, ahi.y);
        sm.Ap[buf][akh][2][arow] = make_uint2(alo.z, ahi.z);
        sm.Ap[buf][akh][3][arow] = make_uint2(alo.w, ahi.w);
        uint32_t lo0 = __byte_perm(w0, w1, 0x5410);
        uint32_t lo1 = __byte_perm(w0, w1, 0x7632);
        uint32_t hi0 = __byte_perm(w2, w3, 0x5410);
        uint32_t hi1 = __byte_perm(w2, w3, 0x7632);
        *(uint4*)&sm.Bp[buf][bks][btg][2 * bcp] = make_uint4(lo0, hi0, lo1, hi1);
    };

    store_tile(0);
    __syncthreads();

    const int nT = Kd >> 5;
    for (int t = 0; t < nT; t++) {
        const int buf = t & 1;
        const bool more = (t + 1 < nT);
        if (more) {
            const __half* ap = aPtr + (t + 1) * 32;
            alo = *(const uint4*)(ap);
            ahi = *(const uint4*)(ap + 8);
            const __half* bp = bPtr + (size_t)(t + 1) * 32 * Nd;
            w0 = *(const uint32_t*)(bp);
            w1 = *(const uint32_t*)(bp + Nd);
            w2 = *(const uint32_t*)(bp + 8 * Nd);
            w3 = *(const uint32_t*)(bp + 9 * Nd);
        }
#pragma unroll
        for (int ks = 0; ks < 2; ks++) {
            uint2 fal[2], fah[2], fb[4];
#pragma unroll
            for (int mi = 0; mi < 2; mi++) {
                fal[mi] = sm.Ap[buf][ks][tg][wm * 32 + mi * 16 + g];
                fah[mi] = sm.Ap[buf][ks][tg][wm * 32 + mi * 16 + g + 8];
            }
#pragma unroll
            for (int nj = 0; nj < 4; nj++)
                fb[nj] = sm.Bp[buf][ks][tg][wn * 32 + nj * 8 + g];
#pragma unroll
            for (int mi = 0; mi < 2; mi++)
#pragma unroll
                for (int nj = 0; nj < 4; nj++)
                    mma_f16(acc[mi][nj],
                            fal[mi].x, fah[mi].x, fal[mi].y, fah[mi].y,
                            fb[nj].x, fb[nj].y);
        }
        if (more) store_tile(buf ^ 1);
        __syncthreads();
    }

#pragma unroll
    for (int mi = 0; mi < 2; mi++) {
        int r0 = m0 + wm * 32 + mi * 16 + g;
#pragma unroll
        for (int nj = 0; nj < 4; nj++) {
            int col = n0 + wn * 32 + nj * 8 + tg * 2;
            float2 bbv = *(const float2*)(bias + col);
            float4 a = acc[mi][nj];
            float2 r0v = *(const float2*)(res + (size_t)r0 * Nd + col);
            float2 r1v = *(const float2*)(res + (size_t)(r0 + 8) * Nd + col);
            float2 o0 = make_float2(a.x + bbv.x + r0v.x, a.y + bbv.y + r0v.y);
            float2 o1 = make_float2(a.z + bbv.x + r1v.x, a.w + bbv.y + r1v.y);
            *(float2*)(C + (size_t)r0 * Nd + col)       = o0;
            *(float2*)(C + (size_t)(r0 + 8) * Nd + col) = o1;
        }
    }
}

// ------------------------ prep (half in, half out) ---------------------------
__global__ void prep_kernel(const __half* __restrict__ qb, const __half* __restrict__ kb,
                            const __half* __restrict__ vb, const float* __restrict__ cos_t,
                            const float* __restrict__ sin_t, const float* __restrict__ c_arr,
                            const float* __restrict__ hash_off,
                            __half* __restrict__ qh, __half* __restrict__ kh,
                            __half* __restrict__ vt) {
    int bn = blockIdx.x;
    int b = bn / N_, n = bn % N_;
    int h = threadIdx.x >> 5, lane = threadIdx.x & 31;
    const float LOG9 = 2.1972245773362196f;
    float cs = cos_t[n * 32 + lane];
    float sn = sin_t[n * 32 + lane];
    float cb = c_arr[b];
    float sqrt_c = fmaxf(sqrtf(cb), EPSV);
    size_t in_off  = (size_t)bn * DIM_ + h * HD_;
    size_t out_off = (((size_t)(b * NH_ + h)) * N_ + n) * HD_;

    {
        float v0 = __half2float(qb[in_off + lane])      + hash_off[h * HD_ + lane]      * LOG9;
        float v1 = __half2float(qb[in_off + lane + 32]) + hash_off[h * HD_ + lane + 32] * LOG9;
        float r0 = v0 * cs - v1 * sn;
        float r1 = v0 * sn + v1 * cs;
        float nrm = sqrtf(warpsum(r0 * r0 + r1 * r1));
        float o0 = 0.f, o1 = 0.f;
        if (nrm >= EPSV) {
            float safe = fmaxf(nrm, EPSV);
            float sc   = __fdividef(tanh_pos(sqrt_c * safe), sqrt_c * safe);
            o0 = sc * r0; o1 = sc * r1;
        }
        qh[out_off + lane] = __float2half_rn(o0);
        qh[out_off + lane + 32] = __float2half_rn(o1);
    }
    {
        float v0 = __half2float(kb[in_off + lane]);
        float v1 = __half2float(kb[in_off + lane + 32]);
        float r0 = v0 * cs - v1 * sn;
        float r1 = v0 * sn + v1 * cs;
        float nrm = sqrtf(warpsum(r0 * r0 + r1 * r1));
        float o0 = 0.f, o1 = 0.f;
        if (nrm >= EPSV) {
            float safe = fmaxf(nrm, EPSV);
            float sc   = __fdividef(tanh_pos(sqrt_c * safe), sqrt_c * safe);
            o0 = sc * r0; o1 = sc * r1;
        }
        kh[out_off + lane] = __float2half_rn(o0);
        kh[out_off + lane + 32] = __float2half_rn(o1);
    }
    vt[out_off + lane]      = vb[in_off + lane];
    vt[out_off + lane + 32] = vb[in_off + lane + 32];
}

// ---------- windowed Poincaré attention (QT=32, tensor-core scores) ----------
#define QT3    32
#define KR3T   96                  // padded key rows (mma N dim)
#define KU_STR 36                  // uint (half2) stride: mma-fragment conflict-free
#define SW_STR 65
#define NT3    ((N_ / QT3) * B_ * NH_)   // 512 tiles = grid
#define RMIN_  5.0000003e-8f             // (1e-7)/(2-1e-7)

__global__ __launch_bounds__(256, 4) void attn5_kernel(
    const __half* __restrict__ qh, const __half* __restrict__ kh,
    const __half* __restrict__ vt, const float* __restrict__ c_arr,
    const float* __restrict__ geo, __half* __restrict__ attn_out) {
    __shared__ uint32_t Ku[KR3T * KU_STR];   // K tile (half2); reused for V
    __shared__ uint32_t Qu[QT3 * KU_STR];    // Q tile (half2)
    __shared__ float Sw[QT3 * SW_STR];
    __shared__ float y2s[KR3T];
    __shared__ float q2s[QT3];

    const int tid = threadIdx.x;
    const int w = tid >> 5, l = tid & 31;
    const int g = l >> 2, tg = l & 3;
    const int wm = w >> 2, wn = w & 3;   // warp grid: 2(q-blocks) x 4(key-tiles)
    const int qi = tid >> 3;             // AV: query
    const int dg = tid & 7;              // AV: dim group

    const int t = blockIdx.x;
    const int bh = t >> 5;
    const int b = bh >> 3, h = bh & 7;
    const int n0 = (t & 31) << 5;
    const __half* Kb = kh + (size_t)bh * (N_ * HD_);
    const __half* Vb = vt + (size_t)bh * (N_ * HD_);
    const __half* Qb = qh + (size_t)bh * (N_ * HD_);

    // ---- K tile -> smem (96 rows incl. zero pad; both-end gn guard)
#pragma unroll
    for (int i = 0; i < 3; i++) {
        int f = tid + i * 256;           // f < 768 = 96 rows x 8 uint-groups
        int row = f >> 3, u4 = (f & 7) * 4;
        int gn = n0 - (WIN_ - 1) + row;
        uint4 val = make_uint4(0u, 0u, 0u, 0u);
        if (gn >= 0 && gn < N_) val = *(const uint4*)(Kb + (size_t)gn * HD_ + u4 * 2);
        uint32_t* d = &Ku[row * KU_STR + u4];
        d[0] = val.x; d[1] = val.y; d[2] = val.z; d[3] = val.w;
    }
    // ---- Q tile -> smem half2
    {
        int row = tid >> 3, u4 = (tid & 7) * 4;
        uint4 qv = *(const uint4*)(Qb + (size_t)(n0 + row) * HD_ + u4 * 2);
        uint32_t* d = &Qu[row * KU_STR + u4];
        d[0] = qv.x; d[1] = qv.y; d[2] = qv.z; d[3] = qv.w;
    }
    // ---- prefetch V into registers (same guards)
    uint4 vreg[3];
#pragma unroll
    for (int i = 0; i < 3; i++) {
        int f = tid + i * 256;
        int row = f >> 3, u4 = (f & 7) * 4;
        int gn = n0 - (WIN_ - 1) + row;
        vreg[i] = make_uint4(0u, 0u, 0u, 0u);
        if (gn >= 0 && gn < N_) vreg[i] = *(const uint4*)(Vb + (size_t)gn * HD_ + u4 * 2);
    }
    __syncthreads();

    // ---- y2 per key row + q2 per query
    for (int row = w; row < KR3T; row += 8) {
        float2 f = unpackh2(Ku[row * KU_STR + l]);
        float s = warpsum(f.x * f.x + f.y * f.y);
        if (l == 0) y2s[row] = s;
    }
    for (int row = w; row < QT3; row += 8) {
        float2 f = unpackh2(Qu[row * KU_STR + l]);
        float s = warpsum(f.x * f.x + f.y * f.y);
        if (l == 0) q2s[row] = s;
    }
    __syncthreads();

    const float cb = c_arr[b];
    const float sc = fmaxf(sqrtf(cb), EPSV);
    const float gs = geo[h];
    const float p2 = gs / sc;
    const float cc = cb * cb;

    // ---- scores via mma: S(32x96) = Q(32x64) . K^T; warp = (wm, 3 n-tiles)
    float4 cacc[3];
#pragma unroll
    for (int j = 0; j < 3; j++) cacc[j] = make_float4(0.f, 0.f, 0.f, 0.f);
#pragma unroll
    for (int ks = 0; ks < 4; ks++) {
        uint32_t a0 = Qu[(wm * 16 + g) * KU_STR + 8 * ks + tg];
        uint32_t a1 = Qu[(wm * 16 + g + 8) * KU_STR + 8 * ks + tg];
        uint32_t a2 = Qu[(wm * 16 + g) * KU_STR + 8 * ks + tg + 4];
        uint32_t a3 = Qu[(wm * 16 + g + 8) * KU_STR + 8 * ks + tg + 4];
#pragma unroll
        for (int j = 0; j < 3; j++) {
            int kbase = (3 * wn + j) * 8;
            uint32_t b0 = Ku[(kbase + g) * KU_STR + 8 * ks + tg];
            uint32_t b1 = Ku[(kbase + g) * KU_STR + 8 * ks + tg + 4];
            mma_f16(cacc[j], a0, a1, a2, a3, b0, b1);
        }
    }
    // ---- banded Poincaré transform on held fragments -> Sw[q][win]
#pragma unroll
    for (int j = 0; j < 3; j++) {
        int kr0 = (3 * wn + j) * 8 + 2 * tg;
        float vals[4] = {cacc[j].x, cacc[j].y, cacc[j].z, cacc[j].w};
#pragma unroll
        for (int e = 0; e < 4; e++) {
            int ql = wm * 16 + g + ((e >= 2) ? 8 : 0);
            int r  = kr0 + (e & 1);
            int win = r - ql;
            if (win >= 0 && win < WIN_) {
                float xyv = vals[e];
                float q2 = q2s[ql];
                float y2 = y2s[r];
                float u  = fmaf(-2.f * cb, xyv, 1.f);
                float A  = fmaf(cb, y2, u);
                float Bc = 1.f - cb * q2;
                float dn2 = fmaf(A * A, q2, fmaf(Bc * Bc, y2, -2.f * A * Bc * xyv));
                float den = fmaxf(fmaf(cc * q2, y2, u), EPSV);
                float s   = sc * sqrt_fast(fmaxf(dn2, 0.f));
                float ratio = __fdividef(den - s, den + s);
                ratio = fmaxf(ratio, RMIN_);
                Sw[ql * SW_STR + win] = p2 * __log2f(ratio);
            }
        }
    }
    __syncthreads();

    // ---- V regs -> smem (overwrite Ku) + softmax, one phase
#pragma unroll
    for (int i = 0; i < 3; i++) {
        int f = tid + i * 256;
        int row = f >> 3, u4 = (f & 7) * 4;
        uint32_t* d = &Ku[row * KU_STR + u4];
        d[0] = vreg[i].x; d[1] = vreg[i].y; d[2] = vreg[i].z; d[3] = vreg[i].w;
    }
#pragma unroll
    for (int qq = 0; qq < 4; qq++) {
        int q = w + qq * 8;
        float s0 = Sw[q * SW_STR + l];
        float s1 = Sw[q * SW_STR + 32 + l];
        float m = warpmax(fmaxf(s0, s1));
        float e0 = exp2f(s0 - m), e1 = exp2f(s1 - m);
        float inv = __fdividef(1.f, warpsum(e0 + e1));
        Sw[q * SW_STR + l] = e0 * inv;
        Sw[q * SW_STR + 32 + l] = e1 * inv;
    }
    __syncthreads();

    // ---- AV: hfma2 with uint4 (LDS.128) V loads, promote every 8 keys
    {
        float accf[8];
#pragma unroll
        for (int j = 0; j < 8; j++) accf[j] = 0.f;
        const float* wrow = &Sw[qi * SW_STR];
        const uint4* vb4 = (const uint4*)&Ku[qi * KU_STR + dg * 4];
#pragma unroll
        for (int ch = 0; ch < 8; ch++) {
            __half2 hacc[4];
            hacc[0] = hacc[1] = hacc[2] = hacc[3] = __half2half2(__float2half(0.f));
#pragma unroll
            for (int k = ch * 8; k < ch * 8 + 8; k++) {
                __half2 wh2 = __float2half2_rn(wrow[k]);
                uint4 vv = *(const uint4*)((const uint32_t*)vb4 + k * KU_STR);
                hacc[0] = __hfma2(wh2, ash2(vv.x), hacc[0]);
                hacc[1] = __hfma2(wh2, ash2(vv.y), hacc[1]);
                hacc[2] = __hfma2(wh2, ash2(vv.z), hacc[2]);
                hacc[3] = __hfma2(wh2, ash2(vv.w), hacc[3]);
            }
#pragma unroll
            for (int u = 0; u < 4; u++) {
                float2 f = __half22float2(hacc[u]);
                accf[2 * u]     += f.x;
                accf[2 * u + 1] += f.y;
            }
        }
        __half* orow = attn_out + ((size_t)(b * N_ + n0 + qi)) * DIM_ + h * HD_ + dg * 8;
        *(uint4*)orow = make_uint4(packh2(accf[0], accf[1]), packh2(accf[2], accf[3]),
                                   packh2(accf[4], accf[5]), packh2(accf[6], accf[7]));
    }
}

// ------------------------ launch --------------------------------------------
extern "C" void kernel_launch(void* const* d_in, const int* in_sizes, int n_in,
                              void* d_out, int out_size) {
    (void)in_sizes; (void)n_in; (void)out_size;
    const float* x     = (const float*)d_in[0];
    const float* fcos  = (const float*)d_in[1];
    const float* fsin  = (const float*)d_in[2];
    const float* c     = (const float*)d_in[3];
    const float* Wq    = (const float*)d_in[4];
    const float* bq    = (const float*)d_in[5];
    const float* Wk    = (const float*)d_in[6];
    const float* bk    = (const float*)d_in[7];
    const float* Wv    = (const float*)d_in[8];
    const float* bv    = (const float*)d_in[9];
    const float* Wo    = (const float*)d_in[10];
    const float* bo    = (const float*)d_in[11];
    const float* W1    = (const float*)d_in[12];
    const float* b1    = (const float*)d_in[13];
    const float* W2    = (const float*)d_in[14];
    const float* b2    = (const float*)d_in[15];
    const float* ln1s  = (const float*)d_in[16];
    const float* ln1b  = (const float*)d_in[17];
    const float* ln2s  = (const float*)d_in[18];
    const float* ln2b  = (const float*)d_in[19];
    const float* geo   = (const float*)d_in[20];
    const float* hasho = (const float*)d_in[21];
    float* out = (float*)d_out;

    __half *xnh, *attnh, *hhh, *midh, *wh, *q, *k, *v, *qh, *kh, *vt;
    float *xout;
    cudaGetSymbolAddress((void**)&xnh,   g_xnh);
    cudaGetSymbolAddress((void**)&q,     g_q);
    cudaGetSymbolAddress((void**)&k,     g_k);
    cudaGetSymbolAddress((void**)&v,     g_v);
    cudaGetSymbolAddress((void**)&qh,    g_qh);
    cudaGetSymbolAddress((void**)&kh,    g_kh);
    cudaGetSymbolAddress((void**)&vt,    g_vt);
    cudaGetSymbolAddress((void**)&attnh, g_attnh);
    cudaGetSymbolAddress((void**)&xout,  g_xout);
    cudaGetSymbolAddress((void**)&hhh,   g_hhh);
    cudaGetSymbolAddress((void**)&midh,  g_midh);
    cudaGetSymbolAddress((void**)&wh,    g_wh);

    // 0+1) fused: LN1 (blocks 0..2047) + weight cvt (blocks 2048..8191)
    ln1_cvtw_kernel<<<8192, 128>>>(x, ln1s, ln1b, xnh,
                                   Wq, Wk, Wv, Wo, W1, W2, wh);

    // 2) fused QKV projections (half out)
    dim3 gqkv(DIM_ / 128, M_ / 128, 3);
    k_gemm_qkv<<<gqkv, 256>>>(xnh, wh, bq, bk, bv, q, k, v);

    // 3) hash + rope + expmap0 + transpose (half in/out)
    prep_kernel<<<M_, 256>>>(q, k, v, fcos, fsin, c, hasho, qh, kh, vt);

    // 4) sliding-window Poincaré attention (tensor-core scores)
    attn5_kernel<<<NT3, 256>>>(qh, kh, vt, c, geo, attnh);

    // 5) Wo projection + residual(x) -> xout (f32)
    dim3 gwo(DIM_ / 64, M_ / 128);
    k_gemm64_res<<<gwo, 256>>>(attnh, wh + WH_O, bo, x, xout, DIM_, DIM_);

    // 6) LN2 (half out)
    ln_kernel<<<M_, 128>>>(xout, ln2s, ln2b, hhh);

    // 7) FFN1 + gelu (half out)
    dim3 gffn1(DFF_ / 128, M_ / 128);
    k_gemm128_gelu<<<gffn1, 256>>>(hhh, wh + WH_1, b1, midh, DFF_, DIM_);

    // 8) FFN2 + residual(xout) -> out (f32)
    k_gemm64_res<<<gwo, 256>>>(midh, wh + WH_2, b2, xout, out, DIM_, DFF_);
}